// round 1
// baseline (speedup 1.0000x reference)
#include <cuda_runtime.h>

// Problem constants (fixed by setup_inputs): x (32, 64, 64, 64) fp32, codebook (1024, 64) fp32
#define DD     64           // vector dim
#define KK     1024         // codebook size
#define BB     32           // batch
#define HWN    4096         // H*W
#define NPTS   (BB * HWN)   // 131072 points
#define KCHUNK 128          // codebook rows staged in shared per iteration (32 KB)

__device__ float g_cbnorm[KK];

// Precompute ||codebook[k]||^2 once per launch (graph-capturable, alloc-free).
__global__ void cbnorm_kernel(const float* __restrict__ cb) {
    int k = blockIdx.x * blockDim.x + threadIdx.x;
    if (k < KK) {
        const float4* row = (const float4*)(cb + (size_t)k * DD);
        float s0 = 0.f, s1 = 0.f, s2 = 0.f, s3 = 0.f;
        #pragma unroll
        for (int q = 0; q < DD / 4; q++) {
            float4 c = row[q];
            s0 = fmaf(c.x, c.x, s0);
            s1 = fmaf(c.y, c.y, s1);
            s2 = fmaf(c.z, c.z, s2);
            s3 = fmaf(c.w, c.w, s3);
        }
        g_cbnorm[k] = (s0 + s1) + (s2 + s3);
    }
}

// One thread per spatial point. Point vector held in registers (64 floats).
// Codebook streamed through shared memory in 128-row chunks; all lanes of a
// warp read the same codebook element -> broadcast, conflict-free.
__global__ void __launch_bounds__(256) vq_kernel(
    const float* __restrict__ x,
    const float* __restrict__ cb,
    float* __restrict__ out,
    int write_idx
) {
    __shared__ float4 scb[KCHUNK * DD / 4];   // 32 KB
    __shared__ float  snorm[KCHUNK];

    int p = blockIdx.x * 256 + threadIdx.x;   // point id, grid exactly covers NPTS
    int b = p >> 12;                           // / HWN
    int n = p & (HWN - 1);                     // % HWN

    // Load this point's 64-d vector: x[b, d, n] with stride HWN floats.
    // Consecutive threads -> consecutive n -> fully coalesced per d.
    const float* xp = x + (size_t)b * (DD * HWN) + n;
    float v[DD];
    #pragma unroll
    for (int d = 0; d < DD; d++) v[d] = xp[(size_t)d * HWN];

    float best = 3.4e38f;
    int   bi   = 0;

    for (int kc = 0; kc < KK; kc += KCHUNK) {
        __syncthreads();
        // Stage 128 codebook rows (32 KB) into shared: 2048 float4, 8 per thread.
        const float4* src = (const float4*)(cb + (size_t)kc * DD);
        #pragma unroll
        for (int i = 0; i < (KCHUNK * DD / 4) / 256; i++)
            scb[threadIdx.x + i * 256] = src[threadIdx.x + i * 256];
        if (threadIdx.x < KCHUNK)
            snorm[threadIdx.x] = g_cbnorm[kc + threadIdx.x];
        __syncthreads();

        #pragma unroll 2
        for (int k = 0; k < KCHUNK; k++) {
            const float4* row = scb + k * (DD / 4);
            float a0 = 0.f, a1 = 0.f, a2 = 0.f, a3 = 0.f;
            #pragma unroll
            for (int q = 0; q < DD / 4; q++) {
                float4 c = row[q];
                a0 = fmaf(v[4 * q + 0], c.x, a0);
                a1 = fmaf(v[4 * q + 1], c.y, a1);
                a2 = fmaf(v[4 * q + 2], c.z, a2);
                a3 = fmaf(v[4 * q + 3], c.w, a3);
            }
            float dot   = (a0 + a1) + (a2 + a3);
            float score = fmaf(-2.f, dot, snorm[k]);   // ||c||^2 - 2 x.c
            if (score < best) { best = score; bi = kc + k; }  // strict <: first index wins ties
        }
    }

    // Write quantized vector back in (B, D, H, W) layout: coalesced per d.
    const float* q = cb + (size_t)bi * DD;
    float* op = out + (size_t)b * (DD * HWN) + n;
    #pragma unroll
    for (int d = 0; d < DD; d++) op[(size_t)d * HWN] = __ldg(q + d);

    // Indices (flattened (B, H, W)) appended after the quantized tensor, as float.
    if (write_idx) out[(size_t)BB * DD * HWN + p] = (float)bi;
}

extern "C" void kernel_launch(void* const* d_in, const int* in_sizes, int n_in,
                              void* d_out, int out_size) {
    const float* x  = (const float*)d_in[0];
    const float* cb = (const float*)d_in[1];
    float* out = (float*)d_out;

    cbnorm_kernel<<<KK / 256, 256>>>(cb);

    int write_idx = (out_size >= BB * DD * HWN + NPTS) ? 1 : 0;
    vq_kernel<<<NPTS / 256, 256>>>(x, cb, out, write_idx);
}

// round 2
// speedup vs baseline: 1.3811x; 1.3811x over previous
#include <cuda_runtime.h>

// Problem constants (fixed): x (32, 64, 64, 64) fp32, codebook (1024, 64) fp32
#define DD     64
#define KK     1024
#define BB     32
#define HWN    4096
#define NPTS   (BB * HWN)

#define PB     128            // points per block
#define KC     64             // codebook rows per chunk
#define NTHR   256            // 16 tx (k) x 16 ty (points)

typedef unsigned long long ull;

__device__ ull g_mhalf[KK];   // dup(-0.5 * ||c_k||^2)

__device__ __forceinline__ void ffma2(ull &acc, ull a, ull b) {
    asm("fma.rn.f32x2 %0, %1, %2, %0;" : "+l"(acc) : "l"(a), "l"(b));
}
__device__ __forceinline__ float f2lo(ull v) { return __uint_as_float((unsigned)v); }
__device__ __forceinline__ float f2hi(ull v) { return __uint_as_float((unsigned)(v >> 32)); }
__device__ __forceinline__ ull fdup(float f) {
    unsigned u = __float_as_uint(f);
    return ((ull)u << 32) | (ull)u;
}

// Precompute dup(-0.5 * ||codebook[k]||^2)
__global__ void cbnorm_kernel(const float* __restrict__ cb) {
    int k = blockIdx.x * blockDim.x + threadIdx.x;
    if (k < KK) {
        const float4* row = (const float4*)(cb + (size_t)k * DD);
        float s0 = 0.f, s1 = 0.f, s2 = 0.f, s3 = 0.f;
        #pragma unroll
        for (int q = 0; q < DD / 4; q++) {
            float4 c = row[q];
            s0 = fmaf(c.x, c.x, s0);
            s1 = fmaf(c.y, c.y, s1);
            s2 = fmaf(c.z, c.z, s2);
            s3 = fmaf(c.w, c.w, s3);
        }
        g_mhalf[k] = fdup(-0.5f * ((s0 + s1) + (s2 + s3)));
    }
}

// Shared layout (dynamic):
//   sx : ull [DD][PB/2]     -- point-pair packed x tile, 64 rows x 64 ull = 32 KB
//   scb: ull [KC][66]       -- duplicated codebook chunk (row padded to 66 ull) = 33 KB
#define SX_ULL   (DD * (PB / 2))
#define SCB_ROW  66
#define SMEM_BYTES ((SX_ULL + KC * SCB_ROW) * 8)

__global__ void __launch_bounds__(NTHR, 2) vq_kernel(
    const float* __restrict__ x,
    const float* __restrict__ cb,
    float* __restrict__ out,
    int write_idx
) {
    extern __shared__ ull smem[];
    ull* sx  = smem;                 // sx[d * 64 + u]
    ull* scb = smem + SX_ULL;        // scb[k * 66 + d]
    __shared__ int sidx[PB];

    const int tid = threadIdx.x;
    const int tx  = tid & 15;        // k dimension
    const int ty  = tid >> 4;        // point dimension

    const int p0 = blockIdx.x * PB;  // first point of block (PB | HWN, so single b)
    const int b  = p0 >> 12;
    const int n0 = p0 & (HWN - 1);

    // ---- Stage x tile: sx[d][u] = (x[b,d,n0+2u], x[b,d,n0+2u+1]) — raw ull copy ----
    {
        const ull* xg = (const ull*)x;
        const size_t base = (size_t)b * DD * (HWN / 2) + (n0 >> 1);
        #pragma unroll
        for (int i = 0; i < SX_ULL / NTHR; i++) {
            int flat = tid + i * NTHR;
            int u = flat & 63, d = flat >> 6;
            sx[d * 64 + u] = xg[base + (size_t)d * (HWN / 2) + u];
        }
    }

    float best[8];
    int   bidx[8];
    #pragma unroll
    for (int i = 0; i < 8; i++) { best[i] = -3.4e38f; bidx[i] = 0; }

    for (int kc = 0; kc < KK; kc += KC) {
        __syncthreads();
        // ---- Stage duplicated codebook chunk: scb[kk][d] = dup(cb[kc+kk][d]) ----
        #pragma unroll
        for (int i = 0; i < (KC * DD) / NTHR; i++) {
            int flat = tid + i * NTHR;
            int d = flat & 63, kk = flat >> 6;
            scb[kk * SCB_ROW + d] = fdup(cb[(size_t)(kc + kk) * DD + d]);
        }
        __syncthreads();

        // ---- acc init with -||c||^2 / 2 ----
        ull acc[4][4];   // [point-pair up][k j];  k = kc + tx + 16*j
        #pragma unroll
        for (int j = 0; j < 4; j++) {
            ull mh = __ldg(&g_mhalf[kc + tx + 16 * j]);
            #pragma unroll
            for (int up = 0; up < 4; up++) acc[up][j] = mh;
        }

        // ---- main loop: 2 d's per iteration ----
        #pragma unroll 8
        for (int d = 0; d < DD; d += 2) {
            ull xa[2][4];
            {
                const ulonglong2* xr0 = (const ulonglong2*)&sx[d * 64 + ty * 4];
                const ulonglong2* xr1 = (const ulonglong2*)&sx[(d + 1) * 64 + ty * 4];
                ulonglong2 a = xr0[0], bq = xr0[1];
                ulonglong2 c = xr1[0], e  = xr1[1];
                xa[0][0] = a.x; xa[0][1] = a.y; xa[0][2] = bq.x; xa[0][3] = bq.y;
                xa[1][0] = c.x; xa[1][1] = c.y; xa[1][2] = e.x;  xa[1][3] = e.y;
            }
            ull cbv[4][2];
            #pragma unroll
            for (int j = 0; j < 4; j++) {
                ulonglong2 c = *(const ulonglong2*)&scb[(tx + 16 * j) * SCB_ROW + d];
                cbv[j][0] = c.x; cbv[j][1] = c.y;
            }
            #pragma unroll
            for (int j = 0; j < 4; j++)
                #pragma unroll
                for (int up = 0; up < 4; up++) {
                    ffma2(acc[up][j], xa[0][up], cbv[j][0]);
                    ffma2(acc[up][j], xa[1][up], cbv[j][1]);
                }
        }

        // ---- epilogue: argmax(dot - norm/2), first-index wins ties ----
        #pragma unroll
        for (int j = 0; j < 4; j++) {
            int k = kc + tx + 16 * j;
            #pragma unroll
            for (int up = 0; up < 4; up++) {
                float sA = f2lo(acc[up][j]);
                float sB = f2hi(acc[up][j]);
                int iA = up * 2, iB = up * 2 + 1;
                if (sA > best[iA] || (sA == best[iA] && k < bidx[iA])) { best[iA] = sA; bidx[iA] = k; }
                if (sB > best[iB] || (sB == best[iB] && k < bidx[iB])) { best[iB] = sB; bidx[iB] = k; }
            }
        }
    }

    // ---- cross-tx reduction (tx lanes live in same 16-lane half-warp) ----
    #pragma unroll
    for (int i = 0; i < 8; i++) {
        #pragma unroll
        for (int m = 8; m >= 1; m >>= 1) {
            float ob = __shfl_xor_sync(0xffffffffu, best[i], m);
            int   oi = __shfl_xor_sync(0xffffffffu, bidx[i], m);
            if (ob > best[i] || (ob == best[i] && oi < bidx[i])) { best[i] = ob; bidx[i] = oi; }
        }
    }
    if (tx == 0) {
        #pragma unroll
        for (int i = 0; i < 8; i++) sidx[ty * 8 + i] = bidx[i];
    }
    __syncthreads();

    // ---- write quantized output (coalesced over points) ----
    {
        float* ob = out + (size_t)b * DD * HWN + n0;
        #pragma unroll
        for (int i = 0; i < (PB * DD) / NTHR; i++) {
            int flat = tid + i * NTHR;
            int pl = flat & (PB - 1), d = flat >> 7;
            ob[(size_t)d * HWN + pl] = __ldg(&cb[(size_t)sidx[pl] * DD + d]);
        }
    }
    // ---- indices appended after quantized tensor (as float) ----
    if (write_idx && tid < PB)
        out[(size_t)BB * DD * HWN + p0 + tid] = (float)sidx[tid];
}

extern "C" void kernel_launch(void* const* d_in, const int* in_sizes, int n_in,
                              void* d_out, int out_size) {
    const float* x  = (const float*)d_in[0];
    const float* cb = (const float*)d_in[1];
    float* out = (float*)d_out;

    static int smem_set = 0;
    if (!smem_set) {
        cudaFuncSetAttribute(vq_kernel, cudaFuncAttributeMaxDynamicSharedMemorySize, SMEM_BYTES);
        smem_set = 1;
    }

    cbnorm_kernel<<<KK / 256, 256>>>(cb);

    int write_idx = (out_size >= BB * DD * HWN + NPTS) ? 1 : 0;
    vq_kernel<<<NPTS / PB, NTHR, SMEM_BYTES>>>(x, cb, out, write_idx);
}